// round 1
// baseline (speedup 1.0000x reference)
#include <cuda_runtime.h>
#include <math.h>

#define BB 4
#define NN 4096
#define FF 512
#define HA 128
#define HV 32

// Scratch (device globals: no allocation allowed)
__device__ float g_hnT[BB][HA][NN];   // normalized h, K-major per batch (8 MB)
__device__ float g_gen[BB];
__device__ float g_part[BB][32];      // per-block critic partial sums (deterministic)

// ---------------------------------------------------------------------------
// gen = leaky_relu(gen_number @ W_gen + b_gen), G = 1
// ---------------------------------------------------------------------------
__global__ void prep_kernel(const float* __restrict__ gen_number,
                            const float* __restrict__ W_gen,
                            const float* __restrict__ b_gen) {
    int t = threadIdx.x;
    if (t < BB) {
        float x = gen_number[t] * W_gen[0] + b_gen[0];
        g_gen[t] = (x > 0.f) ? x : 0.01f * x;
    }
}

// ---------------------------------------------------------------------------
// h = [obs | gen] @ W_act + b_act ; row-normalize ; store hn K-major.
// Block: 256 threads, tile 128 rows x 128 cols (full H_A), K chunks of 32.
// Thread (tx,ty) 16x16 grid, 8x8 micro-tile.
// ---------------------------------------------------------------------------
__global__ __launch_bounds__(256) void h_kernel(const float* __restrict__ obs,
                                                const float* __restrict__ W_act,
                                                const float* __restrict__ b_act) {
    __shared__ float As[128][32];   // [row][kk]
    __shared__ float Bs[32][128];   // [kk][col]
    __shared__ float red[16][128];
    __shared__ float rinv[128];

    const int b  = blockIdx.y;
    const int m0 = blockIdx.x * 128;
    const int tid = threadIdx.x;
    const int tx = tid & 15;
    const int ty = tid >> 4;

    float acc[8][8];
#pragma unroll
    for (int i = 0; i < 8; i++)
#pragma unroll
        for (int j = 0; j < 8; j++) acc[i][j] = 0.f;

    const float* obs_b = obs + ((size_t)b * NN + m0) * FF;

    for (int k0 = 0; k0 < FF; k0 += 32) {
#pragma unroll
        for (int i = 0; i < 4; i++) {
            int f4 = tid + i * 256;            // 0..1023
            int row = f4 >> 3, kg = f4 & 7;
            float4 v = *(const float4*)(obs_b + (size_t)row * FF + k0 + kg * 4);
            *(float4*)&As[row][kg * 4] = v;
        }
#pragma unroll
        for (int i = 0; i < 4; i++) {
            int f4 = tid + i * 256;
            int kk = f4 >> 5, cg = f4 & 31;
            float4 v = *(const float4*)(W_act + (size_t)(k0 + kk) * HA + cg * 4);
            *(float4*)&Bs[kk][cg * 4] = v;
        }
        __syncthreads();
#pragma unroll 8
        for (int kk = 0; kk < 32; kk++) {
            float a[8], w[8];
#pragma unroll
            for (int i = 0; i < 8; i++) a[i] = As[ty * 8 + i][kk];
            float4 w0 = *(float4*)&Bs[kk][tx * 8];
            float4 w1 = *(float4*)&Bs[kk][tx * 8 + 4];
            w[0] = w0.x; w[1] = w0.y; w[2] = w0.z; w[3] = w0.w;
            w[4] = w1.x; w[5] = w1.y; w[6] = w1.z; w[7] = w1.w;
#pragma unroll
            for (int i = 0; i < 8; i++)
#pragma unroll
                for (int j = 0; j < 8; j++)
                    acc[i][j] = fmaf(a[i], w[j], acc[i][j]);
        }
        __syncthreads();
    }

    // gen feature (row 512 of W_act) + bias
    const float gv = g_gen[b];
#pragma unroll
    for (int j = 0; j < 8; j++) {
        int col = tx * 8 + j;
        float add = fmaf(gv, W_act[(size_t)FF * HA + col], b_act[col]);
#pragma unroll
        for (int i = 0; i < 8; i++) acc[i][j] += add;
    }

    // per-row sum of squares: partials across the 16 tx groups
#pragma unroll
    for (int i = 0; i < 8; i++) {
        float s = 0.f;
#pragma unroll
        for (int j = 0; j < 8; j++) s = fmaf(acc[i][j], acc[i][j], s);
        red[tx][ty * 8 + i] = s;
    }
    __syncthreads();
    if (tid < 128) {
        float s = 0.f;
#pragma unroll
        for (int x = 0; x < 16; x++) s += red[x][tid];
        rinv[tid] = 1.f / fmaxf(sqrtf(s), 1e-8f);
    }
    __syncthreads();

    float iv[8];
#pragma unroll
    for (int i = 0; i < 8; i++) iv[i] = rinv[ty * 8 + i];

    // store K-major: hnT[b][col][row]
#pragma unroll
    for (int j = 0; j < 8; j++) {
        int col = tx * 8 + j;
        float4 v0 = make_float4(acc[0][j] * iv[0], acc[1][j] * iv[1],
                                acc[2][j] * iv[2], acc[3][j] * iv[3]);
        float4 v1 = make_float4(acc[4][j] * iv[4], acc[5][j] * iv[5],
                                acc[6][j] * iv[6], acc[7][j] * iv[7]);
        float* p = &g_hnT[b][col][m0 + ty * 8];
        *(float4*)p = v0;
        *(float4*)(p + 4) = v1;
    }
}

// ---------------------------------------------------------------------------
// actor tile: C = -(hn @ hn^T), per batch 4096x4096, K=128.
// Both operands come from K-major hnT -> coalesced loads, conflict-free smem.
// ---------------------------------------------------------------------------
__global__ __launch_bounds__(256) void actor_kernel(float* __restrict__ out) {
    __shared__ float As[32][128];   // [kk][m]
    __shared__ float Bs[32][128];   // [kk][n]

    const int b  = blockIdx.z;
    const int m0 = blockIdx.y * 128;
    const int n0 = blockIdx.x * 128;
    const int tid = threadIdx.x;
    const int tx = tid & 15;
    const int ty = tid >> 4;

    float acc[8][8];
#pragma unroll
    for (int i = 0; i < 8; i++)
#pragma unroll
        for (int j = 0; j < 8; j++) acc[i][j] = 0.f;

    const float* A = &g_hnT[b][0][0];

    for (int k0 = 0; k0 < HA; k0 += 32) {
#pragma unroll
        for (int i = 0; i < 4; i++) {
            int f4 = tid + i * 256;
            int kk = f4 >> 5, mg = f4 & 31;
            const float* src = A + (size_t)(k0 + kk) * NN;
            *(float4*)&As[kk][mg * 4] = *(const float4*)(src + m0 + mg * 4);
            *(float4*)&Bs[kk][mg * 4] = *(const float4*)(src + n0 + mg * 4);
        }
        __syncthreads();
#pragma unroll 4
        for (int kk = 0; kk < 32; kk++) {
            float4 a0 = *(float4*)&As[kk][ty * 8];
            float4 a1 = *(float4*)&As[kk][ty * 8 + 4];
            float4 b0 = *(float4*)&Bs[kk][tx * 8];
            float4 b1 = *(float4*)&Bs[kk][tx * 8 + 4];
            float a[8] = {a0.x, a0.y, a0.z, a0.w, a1.x, a1.y, a1.z, a1.w};
            float w[8] = {b0.x, b0.y, b0.z, b0.w, b1.x, b1.y, b1.z, b1.w};
#pragma unroll
            for (int i = 0; i < 8; i++)
#pragma unroll
                for (int j = 0; j < 8; j++)
                    acc[i][j] = fmaf(a[i], w[j], acc[i][j]);
        }
        __syncthreads();
    }

    size_t base = ((size_t)b * NN + m0 + ty * 8) * NN + n0 + tx * 8;
#pragma unroll
    for (int i = 0; i < 8; i++) {
        float4 v0 = make_float4(-acc[i][0], -acc[i][1], -acc[i][2], -acc[i][3]);
        float4 v1 = make_float4(-acc[i][4], -acc[i][5], -acc[i][6], -acc[i][7]);
        float* p = out + base + (size_t)i * NN;
        *(float4*)p = v0;
        *(float4*)(p + 4) = v1;
    }
}

// ---------------------------------------------------------------------------
// critic: v = relu(feats @ W_v1 + b_v1) @ W_v2 + b_v2 ; mean over N.
// Block: 256 threads, 128 rows x 32 cols, 4x4/thread (tx 0..7, ty 0..31).
// Deterministic two-stage reduction (no float atomics).
// ---------------------------------------------------------------------------
__global__ __launch_bounds__(256) void critic_kernel(const float* __restrict__ obs,
                                                     const float* __restrict__ W_v1,
                                                     const float* __restrict__ b_v1,
                                                     const float* __restrict__ W_v2,
                                                     const float* __restrict__ b_v2) {
    __shared__ float As[128][33];   // padded: conflict-free column reads
    __shared__ float Ws[32][32];
    __shared__ float red[8][128];
    __shared__ float wsum[4];

    const int b  = blockIdx.y;
    const int m0 = blockIdx.x * 128;
    const int tid = threadIdx.x;
    const int tx = tid & 7;
    const int ty = tid >> 3;   // 0..31

    float acc[4][4];
#pragma unroll
    for (int i = 0; i < 4; i++)
#pragma unroll
        for (int j = 0; j < 4; j++) acc[i][j] = 0.f;

    const float* obs_b = obs + ((size_t)b * NN + m0) * FF;

    for (int k0 = 0; k0 < FF; k0 += 32) {
#pragma unroll
        for (int i = 0; i < 4; i++) {
            int f4 = tid + i * 256;
            int row = f4 >> 3, kg = f4 & 7;
            float4 v = *(const float4*)(obs_b + (size_t)row * FF + k0 + kg * 4);
            As[row][kg * 4 + 0] = v.x;
            As[row][kg * 4 + 1] = v.y;
            As[row][kg * 4 + 2] = v.z;
            As[row][kg * 4 + 3] = v.w;
        }
        {
            int kk = tid >> 3, cg = tid & 7;
            *(float4*)&Ws[kk][cg * 4] =
                *(const float4*)(W_v1 + (size_t)(k0 + kk) * HV + cg * 4);
        }
        __syncthreads();
#pragma unroll 8
        for (int kk = 0; kk < 32; kk++) {
            float a[4];
#pragma unroll
            for (int i = 0; i < 4; i++) a[i] = As[ty * 4 + i][kk];
            float4 w = *(float4*)&Ws[kk][tx * 4];
            float wv[4] = {w.x, w.y, w.z, w.w};
#pragma unroll
            for (int i = 0; i < 4; i++)
#pragma unroll
                for (int j = 0; j < 4; j++)
                    acc[i][j] = fmaf(a[i], wv[j], acc[i][j]);
        }
        __syncthreads();
    }

    const float gv = g_gen[b];
#pragma unroll
    for (int i = 0; i < 4; i++) {
        float s = 0.f;
#pragma unroll
        for (int j = 0; j < 4; j++) {
            int col = tx * 4 + j;
            float h = acc[i][j] + fmaf(gv, W_v1[(size_t)FF * HV + col], b_v1[col]);
            h = fmaxf(h, 0.f);
            s = fmaf(h, W_v2[col], s);
        }
        red[tx][ty * 4 + i] = s;
    }
    __syncthreads();
    if (tid < 128) {
        float s = 0.f;
#pragma unroll
        for (int x = 0; x < 8; x++) s += red[x][tid];
        s += b_v2[0];                       // per-row v value
#pragma unroll
        for (int off = 16; off > 0; off >>= 1)
            s += __shfl_down_sync(0xffffffffu, s, off);
        if ((tid & 31) == 0) wsum[tid >> 5] = s;
    }
    __syncthreads();
    if (tid == 0)
        g_part[b][blockIdx.x] = wsum[0] + wsum[1] + wsum[2] + wsum[3];
}

__global__ void finalize_kernel(float* __restrict__ out, int out_size) {
    int b = threadIdx.x;
    if (b < BB) {
        float s = 0.f;
#pragma unroll
        for (int i = 0; i < 32; i++) s += g_part[b][i];
        out[(size_t)out_size - BB + b] = s * (1.f / NN);
    }
}

// ---------------------------------------------------------------------------
extern "C" void kernel_launch(void* const* d_in, const int* in_sizes, int n_in,
                              void* d_out, int out_size) {
    const float* obs        = (const float*)d_in[0];
    const float* gen_number = (const float*)d_in[1];
    const float* W_gen      = (const float*)d_in[2];
    const float* b_gen      = (const float*)d_in[3];
    const float* W_act      = (const float*)d_in[4];
    const float* b_act      = (const float*)d_in[5];
    const float* W_v1       = (const float*)d_in[6];
    const float* b_v1       = (const float*)d_in[7];
    const float* W_v2       = (const float*)d_in[8];
    const float* b_v2       = (const float*)d_in[9];
    float* out = (float*)d_out;

    prep_kernel<<<1, 32>>>(gen_number, W_gen, b_gen);
    h_kernel<<<dim3(NN / 128, BB), 256>>>(obs, W_act, b_act);
    critic_kernel<<<dim3(NN / 128, BB), 256>>>(obs, W_v1, b_v1, W_v2, b_v2);
    actor_kernel<<<dim3(NN / 128, NN / 128, BB), 256>>>(out);
    finalize_kernel<<<1, 32>>>(out, out_size);
}

// round 3
// speedup vs baseline: 2.2356x; 2.2356x over previous
#include <cuda_runtime.h>
#include <math.h>
#include <stdint.h>

#define BB 4
#define NN 4096
#define FF 512
#define HA 128
#define HV 32

// Scratch (device globals: no allocation allowed)
__device__ float g_hn[BB][NN][HA];    // normalized h, row-major, tf32-rounded (8 MB)
__device__ float g_gen[BB];
__device__ float g_part[BB][32];

// ---------------------------------------------------------------------------
__global__ void prep_kernel(const float* __restrict__ gen_number,
                            const float* __restrict__ W_gen,
                            const float* __restrict__ b_gen) {
    int t = threadIdx.x;
    if (t < BB) {
        float x = gen_number[t] * W_gen[0] + b_gen[0];
        g_gen[t] = (x > 0.f) ? x : 0.01f * x;
    }
}

__device__ __forceinline__ float tf32r(float x) {
    uint32_t o;
    asm("cvt.rna.tf32.f32 %0, %1;" : "=r"(o) : "f"(x));
    return __uint_as_float(o);
}

// ---------------------------------------------------------------------------
// FUSED: h = [obs|gen]@W_act+b_act -> normalize -> tf32 -> g_hn (row-major)
//        critic partial: relu([obs|gen]@W_v1+b_v1)@W_v2 summed per block
// ---------------------------------------------------------------------------
__global__ __launch_bounds__(256) void hc_kernel(const float* __restrict__ obs,
                                                 const float* __restrict__ W_act,
                                                 const float* __restrict__ b_act,
                                                 const float* __restrict__ W_v1,
                                                 const float* __restrict__ b_v1,
                                                 const float* __restrict__ W_v2,
                                                 const float* __restrict__ b_v2) {
    __shared__ float As[128][32];
    __shared__ float Bs[32][128];
    __shared__ float Ws[32][32];
    __shared__ float red[16][128];
    __shared__ float rinv[128];
    __shared__ float wsum[4];

    const int b  = blockIdx.y;
    const int m0 = blockIdx.x * 128;
    const int tid = threadIdx.x;
    const int tx = tid & 15;
    const int ty = tid >> 4;

    float acc[8][8];
    float accv[8][2];
#pragma unroll
    for (int i = 0; i < 8; i++) {
#pragma unroll
        for (int j = 0; j < 8; j++) acc[i][j] = 0.f;
        accv[i][0] = 0.f; accv[i][1] = 0.f;
    }

    const float* obs_b = obs + ((size_t)b * NN + m0) * FF;

    for (int k0 = 0; k0 < FF; k0 += 32) {
#pragma unroll
        for (int i = 0; i < 4; i++) {
            int f4 = tid + i * 256;
            int row = f4 >> 3, kg = f4 & 7;
            float4 v = *(const float4*)(obs_b + (size_t)row * FF + k0 + kg * 4);
            *(float4*)&As[row][kg * 4] = v;
        }
#pragma unroll
        for (int i = 0; i < 4; i++) {
            int f4 = tid + i * 256;
            int kk = f4 >> 5, cg = f4 & 31;
            float4 v = *(const float4*)(W_act + (size_t)(k0 + kk) * HA + cg * 4);
            *(float4*)&Bs[kk][cg * 4] = v;
        }
        {
            int kk = tid >> 3, cg = tid & 7;
            *(float4*)&Ws[kk][cg * 4] =
                *(const float4*)(W_v1 + (size_t)(k0 + kk) * HV + cg * 4);
        }
        __syncthreads();
#pragma unroll 8
        for (int kk = 0; kk < 32; kk++) {
            float a[8], w[8];
#pragma unroll
            for (int i = 0; i < 8; i++) a[i] = As[ty * 8 + i][kk];
            float4 w0 = *(float4*)&Bs[kk][tx * 8];
            float4 w1 = *(float4*)&Bs[kk][tx * 8 + 4];
            w[0] = w0.x; w[1] = w0.y; w[2] = w0.z; w[3] = w0.w;
            w[4] = w1.x; w[5] = w1.y; w[6] = w1.z; w[7] = w1.w;
            float2 wv = *(float2*)&Ws[kk][tx * 2];
#pragma unroll
            for (int i = 0; i < 8; i++) {
#pragma unroll
                for (int j = 0; j < 8; j++)
                    acc[i][j] = fmaf(a[i], w[j], acc[i][j]);
                accv[i][0] = fmaf(a[i], wv.x, accv[i][0]);
                accv[i][1] = fmaf(a[i], wv.y, accv[i][1]);
            }
        }
        __syncthreads();
    }

    const float gv = g_gen[b];
#pragma unroll
    for (int j = 0; j < 8; j++) {
        int col = tx * 8 + j;
        float add = fmaf(gv, W_act[(size_t)FF * HA + col], b_act[col]);
#pragma unroll
        for (int i = 0; i < 8; i++) acc[i][j] += add;
    }

    // row norms
#pragma unroll
    for (int i = 0; i < 8; i++) {
        float s = 0.f;
#pragma unroll
        for (int j = 0; j < 8; j++) s = fmaf(acc[i][j], acc[i][j], s);
        red[tx][ty * 8 + i] = s;
    }
    __syncthreads();
    if (tid < 128) {
        float s = 0.f;
#pragma unroll
        for (int x = 0; x < 16; x++) s += red[x][tid];
        rinv[tid] = 1.f / fmaxf(sqrtf(s), 1e-8f);
    }
    __syncthreads();

    float iv[8];
#pragma unroll
    for (int i = 0; i < 8; i++) iv[i] = rinv[ty * 8 + i];

    // store hn row-major, tf32-rounded
#pragma unroll
    for (int i = 0; i < 8; i++) {
        int row = m0 + ty * 8 + i;
        float4 v0 = make_float4(tf32r(acc[i][0] * iv[i]), tf32r(acc[i][1] * iv[i]),
                                tf32r(acc[i][2] * iv[i]), tf32r(acc[i][3] * iv[i]));
        float4 v1 = make_float4(tf32r(acc[i][4] * iv[i]), tf32r(acc[i][5] * iv[i]),
                                tf32r(acc[i][6] * iv[i]), tf32r(acc[i][7] * iv[i]));
        float* p = &g_hn[b][row][tx * 8];
        *(float4*)p = v0;
        *(float4*)(p + 4) = v1;
    }

    // critic epilogue
    float sv[8];
#pragma unroll
    for (int i = 0; i < 8; i++) {
        float s = 0.f;
#pragma unroll
        for (int j = 0; j < 2; j++) {
            int col = tx * 2 + j;
            float hv = accv[i][j] + fmaf(gv, W_v1[(size_t)FF * HV + col], b_v1[col]);
            hv = fmaxf(hv, 0.f);
            s = fmaf(hv, W_v2[col], s);
        }
        sv[i] = s;
    }
    __syncthreads();
#pragma unroll
    for (int i = 0; i < 8; i++) red[tx][ty * 8 + i] = sv[i];
    __syncthreads();
    if (tid < 128) {
        float s = 0.f;
#pragma unroll
        for (int x = 0; x < 16; x++) s += red[x][tid];
        s += b_v2[0];
#pragma unroll
        for (int off = 16; off > 0; off >>= 1)
            s += __shfl_down_sync(0xffffffffu, s, off);
        if ((tid & 31) == 0) wsum[tid >> 5] = s;
    }
    __syncthreads();
    if (tid == 0)
        g_part[b][blockIdx.x] = wsum[0] + wsum[1] + wsum[2] + wsum[3];
}

// ---------------------------------------------------------------------------
// Actor: mma.sync tf32 GEMM. CTA tile 128x128, K=128. A resident, 4 n-tiles
// per CTA, B double-buffered with cp.async.
// ---------------------------------------------------------------------------
#define LDP 132                      // padded row stride (floats)
#define A_OFF 0                      // As[128][132]
#define B_OFF (128 * LDP)            // two B buffers follow
#define BBUF (128 * LDP)
#define SMEM_FLOATS (128 * LDP * 3)
#define SMEM_BYTES (SMEM_FLOATS * 4)  // 202752

__device__ __forceinline__ uint32_t s2u(const void* p) {
    uint32_t a;
    asm("{ .reg .u64 t; cvta.to.shared.u64 t, %1; cvt.u32.u64 %0, t; }"
        : "=r"(a) : "l"(p));
    return a;
}

__device__ __forceinline__ void cp16(uint32_t dst, const float* src) {
    asm volatile("cp.async.cg.shared.global [%0], [%1], 16;"
                 :: "r"(dst), "l"(src));
}

__device__ __forceinline__ void mma_tf32(float* d, const uint32_t* a,
                                         const uint32_t* b) {
    asm volatile(
        "mma.sync.aligned.m16n8k8.row.col.f32.tf32.tf32.f32 "
        "{%0,%1,%2,%3}, {%4,%5,%6,%7}, {%8,%9}, {%0,%1,%2,%3};"
        : "+f"(d[0]), "+f"(d[1]), "+f"(d[2]), "+f"(d[3])
        : "r"(a[0]), "r"(a[1]), "r"(a[2]), "r"(a[3]), "r"(b[0]), "r"(b[1]));
}

__global__ __launch_bounds__(256) void actor_kernel(float* __restrict__ out) {
    extern __shared__ float smem[];
    float* As = smem + A_OFF;
    float* Bs0 = smem + B_OFF;

    const int tid = threadIdx.x;
    const int wid = tid >> 5;
    const int lane = tid & 31;
    const int g = lane >> 2;           // 0..7
    const int t = lane & 3;            // 0..3
    const int wm = wid >> 1;           // 0..3
    const int wn = wid & 1;            // 0..1
    const int b = blockIdx.z;
    const int m0 = blockIdx.y * 128;
    const int ng0 = blockIdx.x * 4;    // first n-tile index of this CTA

    const float* hb = &g_hn[b][0][0];
    const uint32_t sA = s2u(As);
    const uint32_t sB0 = s2u(Bs0);

    // --- issue A + B0 loads (group 0), B1 (group 1) ---
    {
        const float* aSrc = hb + (size_t)m0 * HA;
        const float* bSrc = hb + (size_t)(ng0 * 128) * HA;
#pragma unroll
        for (int i = 0; i < 16; i++) {
            int c = tid + i * 256;                // 0..4095 16B chunks
            int row = c >> 5, kc = c & 31;
            uint32_t doff = (uint32_t)(row * LDP + kc * 4) * 4u;
            cp16(sA + doff, aSrc + row * HA + kc * 4);
        }
#pragma unroll
        for (int i = 0; i < 16; i++) {
            int c = tid + i * 256;
            int row = c >> 5, kc = c & 31;
            uint32_t doff = (uint32_t)(row * LDP + kc * 4) * 4u;
            cp16(sB0 + doff, bSrc + row * HA + kc * 4);
        }
        asm volatile("cp.async.commit_group;" ::: "memory");
        const float* b1Src = hb + (size_t)((ng0 + 1) * 128) * HA;
#pragma unroll
        for (int i = 0; i < 16; i++) {
            int c = tid + i * 256;
            int row = c >> 5, kc = c & 31;
            uint32_t doff = (uint32_t)(BBUF + row * LDP + kc * 4) * 4u;
            cp16(sB0 + doff - (uint32_t)(BBUF * 4) + (uint32_t)(BBUF * 4),
                 b1Src + row * HA + kc * 4);
        }
        asm volatile("cp.async.commit_group;" ::: "memory");
    }
    asm volatile("cp.async.wait_group 1;" ::: "memory");
    __syncthreads();

    const float* Aw = As + (wm * 32) * LDP;

#pragma unroll 1
    for (int nt = 0; nt < 4; nt++) {
        const float* Bw = Bs0 + (nt & 1) * BBUF + (wn * 64) * LDP;

        float acc[2][8][4];
#pragma unroll
        for (int mi = 0; mi < 2; mi++)
#pragma unroll
            for (int ni = 0; ni < 8; ni++)
#pragma unroll
                for (int q = 0; q < 4; q++) acc[mi][ni][q] = 0.f;

#pragma unroll
        for (int ks = 0; ks < 16; ks++) {
            const int kk = ks * 8;
            uint32_t af[2][4];
#pragma unroll
            for (int mi = 0; mi < 2; mi++) {
                const float* ap = Aw + (mi * 16 + g) * LDP + kk + t;
                af[mi][0] = __float_as_uint(ap[0]);
                af[mi][1] = __float_as_uint(ap[8 * LDP]);
                af[mi][2] = __float_as_uint(ap[4]);
                af[mi][3] = __float_as_uint(ap[8 * LDP + 4]);
            }
            uint32_t bf[8][2];
#pragma unroll
            for (int ni = 0; ni < 8; ni++) {
                const float* bp = Bw + (ni * 8 + g) * LDP + kk + t;
                bf[ni][0] = __float_as_uint(bp[0]);
                bf[ni][1] = __float_as_uint(bp[4]);
            }
#pragma unroll
            for (int mi = 0; mi < 2; mi++)
#pragma unroll
                for (int ni = 0; ni < 8; ni++)
                    mma_tf32(acc[mi][ni], af[mi], bf[ni]);
        }
        __syncthreads();   // done reading B buffer (nt&1)

        // prefetch B[nt+2] into the buffer we just freed
        if (nt + 2 < 4) {
            const float* bSrc = hb + (size_t)((ng0 + nt + 2) * 128) * HA;
            uint32_t base = sB0 + (uint32_t)((nt & 1) * BBUF) * 4u;
#pragma unroll
            for (int i = 0; i < 16; i++) {
                int c = tid + i * 256;
                int row = c >> 5, kc = c & 31;
                uint32_t doff = (uint32_t)(row * LDP + kc * 4) * 4u;
                cp16(base + doff, bSrc + row * HA + kc * 4);
            }
            asm volatile("cp.async.commit_group;" ::: "memory");
        }

        // epilogue: negate + direct stores (overlaps with async prefetch)
        {
            const int n0 = (ng0 + nt) * 128 + wn * 64;
            size_t rbase = ((size_t)b * NN + m0 + wm * 32 + g) * NN + n0;
#pragma unroll
            for (int mi = 0; mi < 2; mi++) {
                size_t r0 = rbase + (size_t)(mi * 16) * NN;
#pragma unroll
                for (int ni = 0; ni < 8; ni++) {
                    float2 v0 = make_float2(-acc[mi][ni][0], -acc[mi][ni][1]);
                    float2 v1 = make_float2(-acc[mi][ni][2], -acc[mi][ni][3]);
                    *(float2*)(out + r0 + ni * 8 + 2 * t) = v0;
                    *(float2*)(out + r0 + (size_t)8 * NN + ni * 8 + 2 * t) = v1;
                }
            }
        }

        if (nt < 3) {
            if (nt < 2) {
                asm volatile("cp.async.wait_group 1;" ::: "memory");
            } else {
                asm volatile("cp.async.wait_group 0;" ::: "memory");
            }
            __syncthreads();
        }
    }
}

// ---------------------------------------------------------------------------
__global__ void finalize_kernel(float* __restrict__ out, int out_size) {
    int b = threadIdx.x;
    if (b < BB) {
        float s = 0.f;
#pragma unroll
        for (int i = 0; i < 32; i++) s += g_part[b][i];
        out[(size_t)out_size - BB + b] = s * (1.f / NN);
    }
}

// ---------------------------------------------------------------------------
extern "C" void kernel_launch(void* const* d_in, const int* in_sizes, int n_in,
                              void* d_out, int out_size) {
    const float* obs        = (const float*)d_in[0];
    const float* gen_number = (const float*)d_in[1];
    const float* W_gen      = (const float*)d_in[2];
    const float* b_gen      = (const float*)d_in[3];
    const float* W_act      = (const float*)d_in[4];
    const float* b_act      = (const float*)d_in[5];
    const float* W_v1       = (const float*)d_in[6];
    const float* b_v1       = (const float*)d_in[7];
    const float* W_v2       = (const float*)d_in[8];
    const float* b_v2       = (const float*)d_in[9];
    float* out = (float*)d_out;

    cudaFuncSetAttribute(actor_kernel, cudaFuncAttributeMaxDynamicSharedMemorySize,
                         SMEM_BYTES);

    prep_kernel<<<1, 32>>>(gen_number, W_gen, b_gen);
    hc_kernel<<<dim3(NN / 128, BB), 256>>>(obs, W_act, b_act, W_v1, b_v1, W_v2, b_v2);
    actor_kernel<<<dim3(8, NN / 128, BB), 256, SMEM_BYTES>>>(out);
    finalize_kernel<<<1, 32>>>(out, out_size);
}

// round 4
// speedup vs baseline: 2.9100x; 1.3017x over previous
#include <cuda_runtime.h>
#include <math.h>
#include <stdint.h>

#define BB 4
#define NN 4096
#define FF 512
#define HA 128
#define HV 32

// Scratch (device globals: no allocation allowed)
__device__ float g_hn[BB][NN][HA];    // normalized h, row-major, tf32-rounded (8 MB)
__device__ float g_part[BB][32];

// ---------------------------------------------------------------------------
__device__ __forceinline__ float tf32r(float x) {
    uint32_t o;
    asm("cvt.rna.tf32.f32 %0, %1;" : "=r"(o) : "f"(x));
    return __uint_as_float(o);
}

__device__ __forceinline__ uint32_t s2u(const void* p) {
    uint32_t a;
    asm("{ .reg .u64 t; cvta.to.shared.u64 t, %1; cvt.u32.u64 %0, t; }"
        : "=r"(a) : "l"(p));
    return a;
}

__device__ __forceinline__ void cp16(uint32_t dst, const float* src) {
    asm volatile("cp.async.cg.shared.global [%0], [%1], 16;"
                 :: "r"(dst), "l"(src));
}

__device__ __forceinline__ void mma_tf32(float* d, const uint32_t* a,
                                         const uint32_t* b) {
    asm volatile(
        "mma.sync.aligned.m16n8k8.row.col.f32.tf32.tf32.f32 "
        "{%0,%1,%2,%3}, {%4,%5,%6,%7}, {%8,%9}, {%0,%1,%2,%3};"
        : "+f"(d[0]), "+f"(d[1]), "+f"(d[2]), "+f"(d[3])
        : "r"(a[0]), "r"(a[1]), "r"(a[2]), "r"(a[3]), "r"(b[0]), "r"(b[1]));
}

// ---------------------------------------------------------------------------
// FUSED hc kernel, tensor-core version.
//   h  = [obs|gen] @ W_act + b_act -> normalize -> tf32 -> g_hn
//   cr = relu([obs|gen] @ W_v1 + b_v1) @ W_v2 -> per-block partial sums
// CTA: 128 rows x (128 + 32) cols, K=512 in 16 chunks of 32, cp.async x2 buf.
// 8 warps: 4(m) x 2(n). wn==0 warps also run the critic MMA.
// ---------------------------------------------------------------------------
#define AS0 0
#define AS1 4608            // As: [128][36]
#define BS0 9216
#define BS1 13568           // Bs: [32][136]
#define WS0 17920
#define WS1 19200           // Ws: [32][40]
#define REDO 20480          // [128][8]
#define RINVO 21504         // [128]
#define CREDO 21632         // [128]
#define CWO 21760           // [4]
#define HC_FLOATS 21764
#define HC_SMEM_BYTES (HC_FLOATS * 4)
// staging (epilogue, overlaps AS/BS region): [128][132] = 16896 floats

__global__ __launch_bounds__(256, 1) void hc_kernel(const float* __restrict__ obs,
                                                    const float* __restrict__ gen_number,
                                                    const float* __restrict__ W_gen,
                                                    const float* __restrict__ b_gen,
                                                    const float* __restrict__ W_act,
                                                    const float* __restrict__ b_act,
                                                    const float* __restrict__ W_v1,
                                                    const float* __restrict__ b_v1,
                                                    const float* __restrict__ W_v2,
                                                    const float* __restrict__ b_v2) {
    extern __shared__ float sm[];
    const uint32_t smb = s2u(sm);

    const int b  = blockIdx.y;
    const int m0 = blockIdx.x * 128;
    const int tid = threadIdx.x;
    const int wid = tid >> 5;
    const int lane = tid & 31;
    const int g = lane >> 2;
    const int t = lane & 3;
    const int wm = wid >> 1;
    const int wn = wid & 1;

    const float* obs_b = obs + ((size_t)b * NN + m0) * FF;

    float acc[2][8][4];
    float accv[2][4][4];
#pragma unroll
    for (int mi = 0; mi < 2; mi++) {
#pragma unroll
        for (int ni = 0; ni < 8; ni++)
#pragma unroll
            for (int q = 0; q < 4; q++) acc[mi][ni][q] = 0.f;
#pragma unroll
        for (int ni = 0; ni < 4; ni++)
#pragma unroll
            for (int q = 0; q < 4; q++) accv[mi][ni][q] = 0.f;
    }

    // ---- chunk loader ----
    auto issue = [&](int ck, int buf) {
        const int k0 = ck * 32;
        uint32_t as = smb + (uint32_t)((buf ? AS1 : AS0) * 4);
        uint32_t bs = smb + (uint32_t)((buf ? BS1 : BS0) * 4);
        uint32_t ws = smb + (uint32_t)((buf ? WS1 : WS0) * 4);
#pragma unroll
        for (int i = 0; i < 4; i++) {           // obs: 128x32
            int c = tid + i * 256;
            int row = c >> 3, kc = c & 7;
            cp16(as + (uint32_t)(row * 36 + kc * 4) * 4u,
                 obs_b + (size_t)row * FF + k0 + kc * 4);
        }
#pragma unroll
        for (int i = 0; i < 4; i++) {           // W_act: 32x128 -> [k][n]
            int c = tid + i * 256;
            int kk = c >> 5, cg = c & 31;
            cp16(bs + (uint32_t)(kk * 136 + cg * 4) * 4u,
                 W_act + (size_t)(k0 + kk) * HA + cg * 4);
        }
        {                                       // W_v1: 32x32 -> [k][n]
            int kk = tid >> 3, cg = tid & 7;
            cp16(ws + (uint32_t)(kk * 40 + cg * 4) * 4u,
                 W_v1 + (size_t)(k0 + kk) * HV + cg * 4);
        }
    };

    issue(0, 0);
    asm volatile("cp.async.commit_group;" ::: "memory");
    issue(1, 1);
    asm volatile("cp.async.commit_group;" ::: "memory");
    asm volatile("cp.async.wait_group 1;" ::: "memory");
    __syncthreads();

#pragma unroll 1
    for (int ck = 0; ck < 16; ck++) {
        const int buf = ck & 1;
        const float* A  = sm + (buf ? AS1 : AS0) + wm * 32 * 36;
        const float* Bm = sm + (buf ? BS1 : BS0) + wn * 64;
        const float* Wc = sm + (buf ? WS1 : WS0);
#pragma unroll
        for (int ks = 0; ks < 4; ks++) {
            const int kk = ks * 8;
            uint32_t af[2][4];
#pragma unroll
            for (int mi = 0; mi < 2; mi++) {
                const float* ap = A + (mi * 16 + g) * 36 + kk + t;
                af[mi][0] = __float_as_uint(ap[0]);
                af[mi][1] = __float_as_uint(ap[8 * 36]);
                af[mi][2] = __float_as_uint(ap[4]);
                af[mi][3] = __float_as_uint(ap[8 * 36 + 4]);
            }
            uint32_t bf[8][2];
#pragma unroll
            for (int ni = 0; ni < 8; ni++) {
                const float* bp = Bm + (kk + t) * 136 + ni * 8 + g;
                bf[ni][0] = __float_as_uint(bp[0]);
                bf[ni][1] = __float_as_uint(bp[4 * 136]);
            }
#pragma unroll
            for (int mi = 0; mi < 2; mi++)
#pragma unroll
                for (int ni = 0; ni < 8; ni++)
                    mma_tf32(acc[mi][ni], af[mi], bf[ni]);
            if (wn == 0) {
                uint32_t bc[4][2];
#pragma unroll
                for (int ni = 0; ni < 4; ni++) {
                    const float* bp = Wc + (kk + t) * 40 + ni * 8 + g;
                    bc[ni][0] = __float_as_uint(bp[0]);
                    bc[ni][1] = __float_as_uint(bp[4 * 40]);
                }
#pragma unroll
                for (int mi = 0; mi < 2; mi++)
#pragma unroll
                    for (int ni = 0; ni < 4; ni++)
                        mma_tf32(accv[mi][ni], af[mi], bc[ni]);
            }
        }
        __syncthreads();                         // everyone done reading buf
        if (ck + 2 < 16) issue(ck + 2, buf);
        asm volatile("cp.async.commit_group;" ::: "memory");
        asm volatile("cp.async.wait_group 1;" ::: "memory");
        __syncthreads();
    }

    // ---- epilogue ----
    float gv;
    {
        float x = gen_number[b] * W_gen[0] + b_gen[0];
        gv = (x > 0.f) ? x : 0.01f * x;
    }

    // actor bias + gen feature
#pragma unroll
    for (int ni = 0; ni < 8; ni++) {
        int c0 = wn * 64 + ni * 8 + 2 * t;
        float a0 = fmaf(gv, W_act[(size_t)FF * HA + c0], b_act[c0]);
        float a1 = fmaf(gv, W_act[(size_t)FF * HA + c0 + 1], b_act[c0 + 1]);
#pragma unroll
        for (int mi = 0; mi < 2; mi++) {
            acc[mi][ni][0] += a0; acc[mi][ni][1] += a1;
            acc[mi][ni][2] += a0; acc[mi][ni][3] += a1;
        }
    }

    // row sum-of-squares partials
    float* RED = sm + REDO;
#pragma unroll
    for (int mi = 0; mi < 2; mi++)
#pragma unroll
        for (int d = 0; d < 2; d++) {
            float s = 0.f;
#pragma unroll
            for (int ni = 0; ni < 8; ni++) {
                s = fmaf(acc[mi][ni][2 * d], acc[mi][ni][2 * d], s);
                s = fmaf(acc[mi][ni][2 * d + 1], acc[mi][ni][2 * d + 1], s);
            }
            int row = wm * 32 + mi * 16 + g + 8 * d;
            RED[row * 8 + wn * 4 + t] = s;
        }
    __syncthreads();
    float* RINV = sm + RINVO;
    if (tid < 128) {
        float s = 0.f;
#pragma unroll
        for (int x = 0; x < 8; x++) s += RED[tid * 8 + x];
        RINV[tid] = 1.f / fmaxf(sqrtf(s), 1e-8f);
    }
    __syncthreads();

    // normalize + tf32 round -> stage (overlaps As/Bs, safe after syncs)
    float* STG = sm;
#pragma unroll
    for (int mi = 0; mi < 2; mi++)
#pragma unroll
        for (int d = 0; d < 2; d++) {
            int row = wm * 32 + mi * 16 + g + 8 * d;
            float iv = RINV[row];
#pragma unroll
            for (int ni = 0; ni < 8; ni++) {
                int col = wn * 64 + ni * 8 + 2 * t;
                STG[row * 132 + col]     = tf32r(acc[mi][ni][2 * d] * iv);
                STG[row * 132 + col + 1] = tf32r(acc[mi][ni][2 * d + 1] * iv);
            }
        }

    // critic partials (register-only, no smem hazard)
    float* CRED = sm + CREDO;
    if (wn == 0) {
#pragma unroll
        for (int mi = 0; mi < 2; mi++)
#pragma unroll
            for (int d = 0; d < 2; d++) {
                float cv = 0.f;
#pragma unroll
                for (int ni = 0; ni < 4; ni++) {
#pragma unroll
                    for (int j = 0; j < 2; j++) {
                        int cc = ni * 8 + 2 * t + j;
                        float hvv = accv[mi][ni][2 * d + j] +
                                    fmaf(gv, W_v1[(size_t)FF * HV + cc], b_v1[cc]);
                        hvv = fmaxf(hvv, 0.f);
                        cv = fmaf(hvv, W_v2[cc], cv);
                    }
                }
                cv += __shfl_xor_sync(0xffffffffu, cv, 1);
                cv += __shfl_xor_sync(0xffffffffu, cv, 2);
                if (t == 0) {
                    int row = wm * 32 + mi * 16 + g + 8 * d;
                    CRED[row] = cv + b_v2[0];
                }
            }
    }
    __syncthreads();

    // coalesced copy of staged hn to global
#pragma unroll
    for (int i = 0; i < 16; i++) {
        int idx = tid + i * 256;                 // 0..4095 float4s
        int row = idx >> 5, c4 = idx & 31;
        float4 v = *(float4*)&STG[row * 132 + c4 * 4];
        *(float4*)&g_hn[b][m0 + row][c4 * 4] = v;
    }

    // critic block reduction
    float* CW = sm + CWO;
    if (tid < 128) {
        float v = CRED[tid];
#pragma unroll
        for (int off = 16; off > 0; off >>= 1)
            v += __shfl_down_sync(0xffffffffu, v, off);
        if ((tid & 31) == 0) CW[tid >> 5] = v;
    }
    __syncthreads();
    if (tid == 0)
        g_part[b][blockIdx.x] = CW[0] + CW[1] + CW[2] + CW[3];
}

// ---------------------------------------------------------------------------
// Actor: mma.sync tf32 GEMM (unchanged from R3, proven). CTA tile 128x128,
// A resident, 4 n-tiles per CTA, B double-buffered with cp.async.
// ---------------------------------------------------------------------------
#define LDP 132
#define A_OFF 0
#define B_OFF (128 * LDP)
#define BBUF (128 * LDP)
#define SMEM_FLOATS (128 * LDP * 3)
#define SMEM_BYTES (SMEM_FLOATS * 4)

__global__ __launch_bounds__(256) void actor_kernel(float* __restrict__ out) {
    extern __shared__ float smem[];
    float* As = smem + A_OFF;
    float* Bs0 = smem + B_OFF;

    const int tid = threadIdx.x;
    const int wid = tid >> 5;
    const int lane = tid & 31;
    const int g = lane >> 2;
    const int t = lane & 3;
    const int wm = wid >> 1;
    const int wn = wid & 1;
    const int b = blockIdx.z;
    const int m0 = blockIdx.y * 128;
    const int ng0 = blockIdx.x * 4;

    const float* hb = &g_hn[b][0][0];
    const uint32_t sA = s2u(As);
    const uint32_t sB0 = s2u(Bs0);

    {
        const float* aSrc = hb + (size_t)m0 * HA;
        const float* bSrc = hb + (size_t)(ng0 * 128) * HA;
#pragma unroll
        for (int i = 0; i < 16; i++) {
            int c = tid + i * 256;
            int row = c >> 5, kc = c & 31;
            uint32_t doff = (uint32_t)(row * LDP + kc * 4) * 4u;
            cp16(sA + doff, aSrc + row * HA + kc * 4);
        }
#pragma unroll
        for (int i = 0; i < 16; i++) {
            int c = tid + i * 256;
            int row = c >> 5, kc = c & 31;
            uint32_t doff = (uint32_t)(row * LDP + kc * 4) * 4u;
            cp16(sB0 + doff, bSrc + row * HA + kc * 4);
        }
        asm volatile("cp.async.commit_group;" ::: "memory");
        const float* b1Src = hb + (size_t)((ng0 + 1) * 128) * HA;
        uint32_t base1 = sB0 + (uint32_t)BBUF * 4u;
#pragma unroll
        for (int i = 0; i < 16; i++) {
            int c = tid + i * 256;
            int row = c >> 5, kc = c & 31;
            uint32_t doff = (uint32_t)(row * LDP + kc * 4) * 4u;
            cp16(base1 + doff, b1Src + row * HA + kc * 4);
        }
        asm volatile("cp.async.commit_group;" ::: "memory");
    }
    asm volatile("cp.async.wait_group 1;" ::: "memory");
    __syncthreads();

    const float* Aw = As + (wm * 32) * LDP;

#pragma unroll 1
    for (int nt = 0; nt < 4; nt++) {
        const float* Bw = Bs0 + (nt & 1) * BBUF + (wn * 64) * LDP;

        float acc[2][8][4];
#pragma unroll
        for (int mi = 0; mi < 2; mi++)
#pragma unroll
            for (int ni = 0; ni < 8; ni++)
#pragma unroll
                for (int q = 0; q < 4; q++) acc[mi][ni][q] = 0.f;

#pragma unroll
        for (int ks = 0; ks < 16; ks++) {
            const int kk = ks * 8;
            uint32_t af[2][4];
#pragma unroll
            for (int mi = 0; mi < 2; mi++) {
                const float* ap = Aw + (mi * 16 + g) * LDP + kk + t;
                af[mi][0] = __float_as_uint(ap[0]);
                af[mi][1] = __float_as_uint(ap[8 * LDP]);
                af[mi][2] = __float_as_uint(ap[4]);
                af[mi][3] = __float_as_uint(ap[8 * LDP + 4]);
            }
            uint32_t bf[8][2];
#pragma unroll
            for (int ni = 0; ni < 8; ni++) {
                const float* bp = Bw + (ni * 8 + g) * LDP + kk + t;
                bf[ni][0] = __float_as_uint(bp[0]);
                bf[ni][1] = __float_as_uint(bp[4]);
            }
#pragma unroll
            for (int mi = 0; mi < 2; mi++)
#pragma unroll
                for (int ni = 0; ni < 8; ni++)
                    mma_tf32(acc[mi][ni], af[mi], bf[ni]);
        }
        __syncthreads();

        if (nt + 2 < 4) {
            const float* bSrc = hb + (size_t)((ng0 + nt + 2) * 128) * HA;
            uint32_t base = sB0 + (uint32_t)((nt & 1) * BBUF) * 4u;
#pragma unroll
            for (int i = 0; i < 16; i++) {
                int c = tid + i * 256;
                int row = c >> 5, kc = c & 31;
                uint32_t doff = (uint32_t)(row * LDP + kc * 4) * 4u;
                cp16(base + doff, bSrc + row * HA + kc * 4);
            }
            asm volatile("cp.async.commit_group;" ::: "memory");
        }

        {
            const int n0 = (ng0 + nt) * 128 + wn * 64;
            size_t rbase = ((size_t)b * NN + m0 + wm * 32 + g) * NN + n0;
#pragma unroll
            for (int mi = 0; mi < 2; mi++) {
                size_t r0 = rbase + (size_t)(mi * 16) * NN;
#pragma unroll
                for (int ni = 0; ni < 8; ni++) {
                    float2 v0 = make_float2(-acc[mi][ni][0], -acc[mi][ni][1]);
                    float2 v1 = make_float2(-acc[mi][ni][2], -acc[mi][ni][3]);
                    *(float2*)(out + r0 + ni * 8 + 2 * t) = v0;
                    *(float2*)(out + r0 + (size_t)8 * NN + ni * 8 + 2 * t) = v1;
                }
            }
        }

        if (nt < 3) {
            if (nt < 2) {
                asm volatile("cp.async.wait_group 1;" ::: "memory");
            } else {
                asm volatile("cp.async.wait_group 0;" ::: "memory");
            }
            __syncthreads();
        }
    }
}

// ---------------------------------------------------------------------------
__global__ void finalize_kernel(float* __restrict__ out, int out_size) {
    int b = threadIdx.x;
    if (b < BB) {
        float s = 0.f;
#pragma unroll
        for (int i = 0; i < 32; i++) s += g_part[b][i];
        out[(size_t)out_size - BB + b] = s * (1.f / NN);
    }
}

// ---------------------------------------------------------------------------
extern "C" void kernel_launch(void* const* d_in, const int* in_sizes, int n_in,
                              void* d_out, int out_size) {
    const float* obs        = (const float*)d_in[0];
    const float* gen_number = (const float*)d_in[1];
    const float* W_gen      = (const float*)d_in[2];
    const float* b_gen      = (const float*)d_in[3];
    const float* W_act      = (const float*)d_in[4];
    const float* b_act      = (const float*)d_in[5];
    const float* W_v1       = (const float*)d_in[6];
    const float* b_v1       = (const float*)d_in[7];
    const float* W_v2       = (const float*)d_in[8];
    const float* b_v2       = (const float*)d_in[9];
    float* out = (float*)d_out;

    cudaFuncSetAttribute(hc_kernel, cudaFuncAttributeMaxDynamicSharedMemorySize,
                         HC_SMEM_BYTES);
    cudaFuncSetAttribute(actor_kernel, cudaFuncAttributeMaxDynamicSharedMemorySize,
                         SMEM_BYTES);

    hc_kernel<<<dim3(NN / 128, BB), 256, HC_SMEM_BYTES>>>(
        obs, gen_number, W_gen, b_gen, W_act, b_act, W_v1, b_v1, W_v2, b_v2);
    actor_kernel<<<dim3(8, NN / 128, BB), 256, SMEM_BYTES>>>(out);
    finalize_kernel<<<1, 32>>>(out, out_size);
}

// round 5
// speedup vs baseline: 3.6962x; 1.2701x over previous
#include <cuda_runtime.h>
#include <math.h>
#include <stdint.h>

#define BB 4
#define NN 4096
#define FF 512
#define HA 128
#define HV 32

// Scratch (device globals: no allocation allowed)
__device__ float g_hn[BB][NN][HA];    // normalized h, row-major, tf32-rounded (8 MB)
__device__ float g_part[BB][32];

// ---------------------------------------------------------------------------
__device__ __forceinline__ float tf32r(float x) {
    uint32_t o;
    asm("cvt.rna.tf32.f32 %0, %1;" : "=r"(o) : "f"(x));
    return __uint_as_float(o);
}

__device__ __forceinline__ uint32_t s2u(const void* p) {
    uint32_t a;
    asm("{ .reg .u64 t; cvta.to.shared.u64 t, %1; cvt.u32.u64 %0, t; }"
        : "=r"(a) : "l"(p));
    return a;
}

__device__ __forceinline__ void cp16(uint32_t dst, const float* src) {
    asm volatile("cp.async.cg.shared.global [%0], [%1], 16;"
                 :: "r"(dst), "l"(src));
}

__device__ __forceinline__ void mma_tf32(float* d, const uint32_t* a,
                                         const uint32_t* b) {
    asm volatile(
        "mma.sync.aligned.m16n8k8.row.col.f32.tf32.tf32.f32 "
        "{%0,%1,%2,%3}, {%4,%5,%6,%7}, {%8,%9}, {%0,%1,%2,%3};"
        : "+f"(d[0]), "+f"(d[1]), "+f"(d[2]), "+f"(d[3])
        : "r"(a[0]), "r"(a[1]), "r"(a[2]), "r"(a[3]), "r"(b[0]), "r"(b[1]));
}

// ---------------------------------------------------------------------------
// FUSED hc kernel (unchanged from R4, proven 32us).
// ---------------------------------------------------------------------------
#define AS0 0
#define AS1 4608            // As: [128][36]
#define BS0 9216
#define BS1 13568           // Bs: [32][136]
#define WS0 17920
#define WS1 19200           // Ws: [32][40]
#define REDO 20480          // [128][8]
#define RINVO 21504         // [128]
#define CREDO 21632         // [128]
#define CWO 21760           // [4]
#define HC_FLOATS 21764
#define HC_SMEM_BYTES (HC_FLOATS * 4)

__global__ __launch_bounds__(256, 1) void hc_kernel(const float* __restrict__ obs,
                                                    const float* __restrict__ gen_number,
                                                    const float* __restrict__ W_gen,
                                                    const float* __restrict__ b_gen,
                                                    const float* __restrict__ W_act,
                                                    const float* __restrict__ b_act,
                                                    const float* __restrict__ W_v1,
                                                    const float* __restrict__ b_v1,
                                                    const float* __restrict__ W_v2,
                                                    const float* __restrict__ b_v2) {
    extern __shared__ float sm[];
    const uint32_t smb = s2u(sm);

    const int b  = blockIdx.y;
    const int m0 = blockIdx.x * 128;
    const int tid = threadIdx.x;
    const int wid = tid >> 5;
    const int lane = tid & 31;
    const int g = lane >> 2;
    const int t = lane & 3;
    const int wm = wid >> 1;
    const int wn = wid & 1;

    const float* obs_b = obs + ((size_t)b * NN + m0) * FF;

    float acc[2][8][4];
    float accv[2][4][4];
#pragma unroll
    for (int mi = 0; mi < 2; mi++) {
#pragma unroll
        for (int ni = 0; ni < 8; ni++)
#pragma unroll
            for (int q = 0; q < 4; q++) acc[mi][ni][q] = 0.f;
#pragma unroll
        for (int ni = 0; ni < 4; ni++)
#pragma unroll
            for (int q = 0; q < 4; q++) accv[mi][ni][q] = 0.f;
    }

    auto issue = [&](int ck, int buf) {
        const int k0 = ck * 32;
        uint32_t as = smb + (uint32_t)((buf ? AS1 : AS0) * 4);
        uint32_t bs = smb + (uint32_t)((buf ? BS1 : BS0) * 4);
        uint32_t ws = smb + (uint32_t)((buf ? WS1 : WS0) * 4);
#pragma unroll
        for (int i = 0; i < 4; i++) {
            int c = tid + i * 256;
            int row = c >> 3, kc = c & 7;
            cp16(as + (uint32_t)(row * 36 + kc * 4) * 4u,
                 obs_b + (size_t)row * FF + k0 + kc * 4);
        }
#pragma unroll
        for (int i = 0; i < 4; i++) {
            int c = tid + i * 256;
            int kk = c >> 5, cg = c & 31;
            cp16(bs + (uint32_t)(kk * 136 + cg * 4) * 4u,
                 W_act + (size_t)(k0 + kk) * HA + cg * 4);
        }
        {
            int kk = tid >> 3, cg = tid & 7;
            cp16(ws + (uint32_t)(kk * 40 + cg * 4) * 4u,
                 W_v1 + (size_t)(k0 + kk) * HV + cg * 4);
        }
    };

    issue(0, 0);
    asm volatile("cp.async.commit_group;" ::: "memory");
    issue(1, 1);
    asm volatile("cp.async.commit_group;" ::: "memory");
    asm volatile("cp.async.wait_group 1;" ::: "memory");
    __syncthreads();

#pragma unroll 1
    for (int ck = 0; ck < 16; ck++) {
        const int buf = ck & 1;
        const float* A  = sm + (buf ? AS1 : AS0) + wm * 32 * 36;
        const float* Bm = sm + (buf ? BS1 : BS0) + wn * 64;
        const float* Wc = sm + (buf ? WS1 : WS0);
#pragma unroll
        for (int ks = 0; ks < 4; ks++) {
            const int kk = ks * 8;
            uint32_t af[2][4];
#pragma unroll
            for (int mi = 0; mi < 2; mi++) {
                const float* ap = A + (mi * 16 + g) * 36 + kk + t;
                af[mi][0] = __float_as_uint(ap[0]);
                af[mi][1] = __float_as_uint(ap[8 * 36]);
                af[mi][2] = __float_as_uint(ap[4]);
                af[mi][3] = __float_as_uint(ap[8 * 36 + 4]);
            }
            uint32_t bf[8][2];
#pragma unroll
            for (int ni = 0; ni < 8; ni++) {
                const float* bp = Bm + (kk + t) * 136 + ni * 8 + g;
                bf[ni][0] = __float_as_uint(bp[0]);
                bf[ni][1] = __float_as_uint(bp[4 * 136]);
            }
#pragma unroll
            for (int mi = 0; mi < 2; mi++)
#pragma unroll
                for (int ni = 0; ni < 8; ni++)
                    mma_tf32(acc[mi][ni], af[mi], bf[ni]);
            if (wn == 0) {
                uint32_t bc[4][2];
#pragma unroll
                for (int ni = 0; ni < 4; ni++) {
                    const float* bp = Wc + (kk + t) * 40 + ni * 8 + g;
                    bc[ni][0] = __float_as_uint(bp[0]);
                    bc[ni][1] = __float_as_uint(bp[4 * 40]);
                }
#pragma unroll
                for (int mi = 0; mi < 2; mi++)
#pragma unroll
                    for (int ni = 0; ni < 4; ni++)
                        mma_tf32(accv[mi][ni], af[mi], bc[ni]);
            }
        }
        __syncthreads();
        if (ck + 2 < 16) issue(ck + 2, buf);
        asm volatile("cp.async.commit_group;" ::: "memory");
        asm volatile("cp.async.wait_group 1;" ::: "memory");
        __syncthreads();
    }

    float gv;
    {
        float x = gen_number[b] * W_gen[0] + b_gen[0];
        gv = (x > 0.f) ? x : 0.01f * x;
    }

#pragma unroll
    for (int ni = 0; ni < 8; ni++) {
        int c0 = wn * 64 + ni * 8 + 2 * t;
        float a0 = fmaf(gv, W_act[(size_t)FF * HA + c0], b_act[c0]);
        float a1 = fmaf(gv, W_act[(size_t)FF * HA + c0 + 1], b_act[c0 + 1]);
#pragma unroll
        for (int mi = 0; mi < 2; mi++) {
            acc[mi][ni][0] += a0; acc[mi][ni][1] += a1;
            acc[mi][ni][2] += a0; acc[mi][ni][3] += a1;
        }
    }

    float* RED = sm + REDO;
#pragma unroll
    for (int mi = 0; mi < 2; mi++)
#pragma unroll
        for (int d = 0; d < 2; d++) {
            float s = 0.f;
#pragma unroll
            for (int ni = 0; ni < 8; ni++) {
                s = fmaf(acc[mi][ni][2 * d], acc[mi][ni][2 * d], s);
                s = fmaf(acc[mi][ni][2 * d + 1], acc[mi][ni][2 * d + 1], s);
            }
            int row = wm * 32 + mi * 16 + g + 8 * d;
            RED[row * 8 + wn * 4 + t] = s;
        }
    __syncthreads();
    float* RINV = sm + RINVO;
    if (tid < 128) {
        float s = 0.f;
#pragma unroll
        for (int x = 0; x < 8; x++) s += RED[tid * 8 + x];
        RINV[tid] = 1.f / fmaxf(sqrtf(s), 1e-8f);
    }
    __syncthreads();

    float* STG = sm;
#pragma unroll
    for (int mi = 0; mi < 2; mi++)
#pragma unroll
        for (int d = 0; d < 2; d++) {
            int row = wm * 32 + mi * 16 + g + 8 * d;
            float iv = RINV[row];
#pragma unroll
            for (int ni = 0; ni < 8; ni++) {
                int col = wn * 64 + ni * 8 + 2 * t;
                STG[row * 132 + col]     = tf32r(acc[mi][ni][2 * d] * iv);
                STG[row * 132 + col + 1] = tf32r(acc[mi][ni][2 * d + 1] * iv);
            }
        }

    float* CRED = sm + CREDO;
    if (wn == 0) {
#pragma unroll
        for (int mi = 0; mi < 2; mi++)
#pragma unroll
            for (int d = 0; d < 2; d++) {
                float cv = 0.f;
#pragma unroll
                for (int ni = 0; ni < 4; ni++) {
#pragma unroll
                    for (int j = 0; j < 2; j++) {
                        int cc = ni * 8 + 2 * t + j;
                        float hvv = accv[mi][ni][2 * d + j] +
                                    fmaf(gv, W_v1[(size_t)FF * HV + cc], b_v1[cc]);
                        hvv = fmaxf(hvv, 0.f);
                        cv = fmaf(hvv, W_v2[cc], cv);
                    }
                }
                cv += __shfl_xor_sync(0xffffffffu, cv, 1);
                cv += __shfl_xor_sync(0xffffffffu, cv, 2);
                if (t == 0) {
                    int row = wm * 32 + mi * 16 + g + 8 * d;
                    CRED[row] = cv + b_v2[0];
                }
            }
    }
    __syncthreads();

#pragma unroll
    for (int i = 0; i < 16; i++) {
        int idx = tid + i * 256;
        int row = idx >> 5, c4 = idx & 31;
        float4 v = *(float4*)&STG[row * 132 + c4 * 4];
        *(float4*)&g_hn[b][m0 + row][c4 * 4] = v;
    }

    float* CW = sm + CWO;
    if (tid < 128) {
        float v = CRED[tid];
#pragma unroll
        for (int off = 16; off > 0; off >>= 1)
            v += __shfl_down_sync(0xffffffffu, v, off);
        if ((tid & 31) == 0) CW[tid >> 5] = v;
    }
    __syncthreads();
    if (tid == 0)
        g_part[b][blockIdx.x] = CW[0] + CW[1] + CW[2] + CW[3];
}

// ---------------------------------------------------------------------------
// Actor v2: symmetric. Only tiles (i,j) with j>=i are computed; off-diagonal
// tiles are stored twice (direct + smem-staged transpose). CTA = row-strip i
// chunk of <=4 j-tiles, A resident, B double-buffered. 144 chunks/batch.
// ---------------------------------------------------------------------------
#define LDP 132
#define BBUF (128 * LDP)
#define SMEM_FLOATS (128 * LDP * 3)
#define SMEM_BYTES (SMEM_FLOATS * 4)

__global__ __launch_bounds__(256) void actor_kernel(float* __restrict__ out,
                                                    int out_size) {
    extern __shared__ float smem[];
    float* As = smem;
    float* Bs0 = smem + 128 * LDP;

    const int tid = threadIdx.x;
    const int wid = tid >> 5;
    const int lane = tid & 31;
    const int g = lane >> 2;
    const int t = lane & 3;
    const int wm = wid >> 1;
    const int wn = wid & 1;
    const int b = blockIdx.y;
    const int cid = blockIdx.x;

    // fold critic finalize into one CTA (g_part written by previous launch)
    if (cid == 0 && b == 0 && tid < BB) {
        float s = 0.f;
#pragma unroll
        for (int k = 0; k < 32; k++) s += g_part[tid][k];
        out[(size_t)out_size - BB + tid] = s * (1.f / NN);
    }

    // decode chunk -> (row tile i, first col tile j0)
    int i = 0, j0;
    {
        int c = cid, ch;
        while (c >= (ch = (32 - i + 3) >> 2)) { c -= ch; i++; }
        j0 = i + 4 * c;
    }
    const int nT = min(4, 32 - j0);

    const float* hb = &g_hn[b][0][0];
    const uint32_t sA = s2u(As);
    const uint32_t sB0 = s2u(Bs0);

    // prologue: A (row strip i) + B[j0] in group 0; B[j0+1] in group 1
    {
        const float* aSrc = hb + (size_t)(i * 128) * HA;
        const float* bSrc = hb + (size_t)(j0 * 128) * HA;
#pragma unroll
        for (int it = 0; it < 16; it++) {
            int c = tid + it * 256;
            int row = c >> 5, kc = c & 31;
            uint32_t doff = (uint32_t)(row * LDP + kc * 4) * 4u;
            cp16(sA + doff, aSrc + row * HA + kc * 4);
        }
#pragma unroll
        for (int it = 0; it < 16; it++) {
            int c = tid + it * 256;
            int row = c >> 5, kc = c & 31;
            uint32_t doff = (uint32_t)(row * LDP + kc * 4) * 4u;
            cp16(sB0 + doff, bSrc + row * HA + kc * 4);
        }
        asm volatile("cp.async.commit_group;" ::: "memory");
        if (nT > 1) {
            const float* b1Src = hb + (size_t)((j0 + 1) * 128) * HA;
            uint32_t base1 = sB0 + (uint32_t)BBUF * 4u;
#pragma unroll
            for (int it = 0; it < 16; it++) {
                int c = tid + it * 256;
                int row = c >> 5, kc = c & 31;
                uint32_t doff = (uint32_t)(row * LDP + kc * 4) * 4u;
                cp16(base1 + doff, b1Src + row * HA + kc * 4);
            }
        }
        asm volatile("cp.async.commit_group;" ::: "memory");
    }
    asm volatile("cp.async.wait_group 1;" ::: "memory");
    __syncthreads();

    const float* Aw = As + (wm * 32) * LDP;

#pragma unroll 1
    for (int nt = 0; nt < nT; nt++) {
        const int j = j0 + nt;
        const int buf = nt & 1;
        const float* Bw = Bs0 + buf * BBUF + (wn * 64) * LDP;

        float acc[2][8][4];
#pragma unroll
        for (int mi = 0; mi < 2; mi++)
#pragma unroll
            for (int ni = 0; ni < 8; ni++)
#pragma unroll
                for (int q = 0; q < 4; q++) acc[mi][ni][q] = 0.f;

#pragma unroll
        for (int ks = 0; ks < 16; ks++) {
            const int kk = ks * 8;
            uint32_t af[2][4];
#pragma unroll
            for (int mi = 0; mi < 2; mi++) {
                const float* ap = Aw + (mi * 16 + g) * LDP + kk + t;
                af[mi][0] = __float_as_uint(ap[0]);
                af[mi][1] = __float_as_uint(ap[8 * LDP]);
                af[mi][2] = __float_as_uint(ap[4]);
                af[mi][3] = __float_as_uint(ap[8 * LDP + 4]);
            }
            uint32_t bf[8][2];
#pragma unroll
            for (int ni = 0; ni < 8; ni++) {
                const float* bp = Bw + (ni * 8 + g) * LDP + kk + t;
                bf[ni][0] = __float_as_uint(bp[0]);
                bf[ni][1] = __float_as_uint(bp[4]);
            }
#pragma unroll
            for (int mi = 0; mi < 2; mi++)
#pragma unroll
                for (int ni = 0; ni < 8; ni++)
                    mma_tf32(acc[mi][ni], af[mi], bf[ni]);
        }
        __syncthreads();          // everyone done reading B[buf]

        // direct store: tile (i, j), coalesced from registers
        {
            const int n0 = j * 128 + wn * 64;
            size_t rbase = ((size_t)b * NN + i * 128 + wm * 32 + g) * NN + n0;
#pragma unroll
            for (int mi = 0; mi < 2; mi++) {
                size_t r0 = rbase + (size_t)(mi * 16) * NN;
#pragma unroll
                for (int ni = 0; ni < 8; ni++) {
                    float2 v0 = make_float2(-acc[mi][ni][0], -acc[mi][ni][1]);
                    float2 v1 = make_float2(-acc[mi][ni][2], -acc[mi][ni][3]);
                    *(float2*)(out + r0 + ni * 8 + 2 * t) = v0;
                    *(float2*)(out + r0 + (size_t)8 * NN + ni * 8 + 2 * t) = v1;
                }
            }
        }

        if (j > i) {
            // stage transposed tile into the just-freed B[buf]: STG[c][r]
            float* STGb = Bs0 + buf * BBUF;
#pragma unroll
            for (int mi = 0; mi < 2; mi++)
#pragma unroll
                for (int ni = 0; ni < 8; ni++) {
                    int c0 = wn * 64 + ni * 8 + 2 * t;
                    int r0 = wm * 32 + mi * 16 + g;
                    STGb[(c0)     * LDP + r0]     = -acc[mi][ni][0];
                    STGb[(c0 + 1) * LDP + r0]     = -acc[mi][ni][1];
                    STGb[(c0)     * LDP + r0 + 8] = -acc[mi][ni][2];
                    STGb[(c0 + 1) * LDP + r0 + 8] = -acc[mi][ni][3];
                }
            __syncthreads();
            // mirrored store: tile (j, i), coalesced
            size_t tbase = ((size_t)b * NN + j * 128) * NN + i * 128;
#pragma unroll
            for (int it = 0; it < 16; it++) {
                int idx = tid + it * 256;
                int c = idx >> 5, q4 = idx & 31;
                float4 v = *(float4*)&STGb[c * LDP + q4 * 4];
                *(float4*)(out + tbase + (size_t)c * NN + q4 * 4) = v;
            }
            __syncthreads();      // staging reads done before prefetch reuses buf
        }

        // prefetch B[j0+nt+2] into B[buf]
        if (nt + 2 < nT) {
            const float* bSrc = hb + (size_t)((j0 + nt + 2) * 128) * HA;
            uint32_t base = sB0 + (uint32_t)(buf * BBUF) * 4u;
#pragma unroll
            for (int it = 0; it < 16; it++) {
                int c = tid + it * 256;
                int row = c >> 5, kc = c & 31;
                uint32_t doff = (uint32_t)(row * LDP + kc * 4) * 4u;
                cp16(base + doff, bSrc + row * HA + kc * 4);
            }
        }
        asm volatile("cp.async.commit_group;" ::: "memory");

        if (nt < nT - 1) {
            asm volatile("cp.async.wait_group 1;" ::: "memory");
            __syncthreads();
        }
    }
}

// ---------------------------------------------------------------------------
extern "C" void kernel_launch(void* const* d_in, const int* in_sizes, int n_in,
                              void* d_out, int out_size) {
    const float* obs        = (const float*)d_in[0];
    const float* gen_number = (const float*)d_in[1];
    const float* W_gen      = (const float*)d_in[2];
    const float* b_gen      = (const float*)d_in[3];
    const float* W_act      = (const float*)d_in[4];
    const float* b_act      = (const float*)d_in[5];
    const float* W_v1       = (const float*)d_in[6];
    const float* b_v1       = (const float*)d_in[7];
    const float* W_v2       = (const float*)d_in[8];
    const float* b_v2       = (const float*)d_in[9];
    float* out = (float*)d_out;

    cudaFuncSetAttribute(hc_kernel, cudaFuncAttributeMaxDynamicSharedMemorySize,
                         HC_SMEM_BYTES);
    cudaFuncSetAttribute(actor_kernel, cudaFuncAttributeMaxDynamicSharedMemorySize,
                         SMEM_BYTES);

    hc_kernel<<<dim3(NN / 128, BB), 256, HC_SMEM_BYTES>>>(
        obs, gen_number, W_gen, b_gen, W_act, b_act, W_v1, b_v1, W_v2, b_v2);
    actor_kernel<<<dim3(144, BB), 256, SMEM_BYTES>>>(out, out_size);
}